// round 2
// baseline (speedup 1.0000x reference)
#include <cuda_runtime.h>
#include <math.h>

#define S_LEN 2048
#define DM    1024
#define NH    16
#define DK    64

// Scratch (no allocations allowed). 4 x 8 MB fp32.
__device__ float g_Q[S_LEN * DM];
__device__ float g_K[S_LEN * DM];
__device__ float g_V[S_LEN * DM];
__device__ float g_ctx[S_LEN * DM];

// ---------------------------------------------------------------------------
// Tiled SGEMM.  C[m][n] = alpha * sum_k A[m][k] * B'[k][n]  (+ bias[n])
//   TRANSB=true :  B'[k][n] = B[n][k]   (NT, e.g. X @ W^T, Q @ K^T)
//   TRANSB=false:  B'[k][n] = B[k][n]   (NN, e.g. attn @ V)
// Batched over blockIdx.z via element strides sA/sB/sC.
// All problem dims here are multiples of the tile sizes (no bounds checks).
// ---------------------------------------------------------------------------
template <bool TRANSB, bool BIAS>
__global__ __launch_bounds__(256)
void sgemm_kernel(const float* __restrict__ A, const float* __restrict__ B,
                  const float* __restrict__ bias, float* __restrict__ C,
                  int M, int N, int K, int lda, int ldb, int ldc,
                  long sA, long sB, long sC, float alpha)
{
    constexpr int BM = 64, BN = 64, BK = 16, TM = 4, TN = 4;
    __shared__ float As[BK][BM];
    __shared__ float Bs[BK][BN];

    A += (long)blockIdx.z * sA;
    B += (long)blockIdx.z * sB;
    C += (long)blockIdx.z * sC;

    const int row0 = blockIdx.y * BM;
    const int col0 = blockIdx.x * BN;
    const int tid  = threadIdx.x;
    const int tx   = tid & 15;   // 0..15 -> N direction
    const int ty   = tid >> 4;   // 0..15 -> M direction

    float acc[TM][TN];
#pragma unroll
    for (int i = 0; i < TM; i++)
#pragma unroll
        for (int j = 0; j < TN; j++) acc[i][j] = 0.f;

    for (int k0 = 0; k0 < K; k0 += BK) {
        // Load A tile: BM x BK (row-major source, k contiguous)
#pragma unroll
        for (int i = tid; i < BM * BK; i += 256) {
            int m = i >> 4, k = i & 15;
            As[k][m] = A[(long)(row0 + m) * lda + (k0 + k)];
        }
        if (TRANSB) {
#pragma unroll
            for (int i = tid; i < BN * BK; i += 256) {
                int n = i >> 4, k = i & 15;
                Bs[k][n] = B[(long)(col0 + n) * ldb + (k0 + k)];
            }
        } else {
#pragma unroll
            for (int i = tid; i < BN * BK; i += 256) {
                int k = i >> 6, n = i & 63;
                Bs[k][n] = B[(long)(k0 + k) * ldb + (col0 + n)];
            }
        }
        __syncthreads();

#pragma unroll
        for (int k = 0; k < BK; k++) {
            float a[TM], b[TN];
#pragma unroll
            for (int i = 0; i < TM; i++) a[i] = As[k][ty * TM + i];
#pragma unroll
            for (int j = 0; j < TN; j++) b[j] = Bs[k][tx * TN + j];
#pragma unroll
            for (int i = 0; i < TM; i++)
#pragma unroll
                for (int j = 0; j < TN; j++) acc[i][j] = fmaf(a[i], b[j], acc[i][j]);
        }
        __syncthreads();
    }

#pragma unroll
    for (int i = 0; i < TM; i++) {
        int m = row0 + ty * TM + i;
#pragma unroll
        for (int j = 0; j < TN; j++) {
            int n = col0 + tx * TN + j;
            float v = acc[i][j] * alpha;
            if (BIAS) v += bias[n];
            C[(long)m * ldc + n] = v;
        }
    }
}

// ---------------------------------------------------------------------------
// RoPE in place on Q and K.  One thread per (s, h, i) with i in [0,32):
//   inv_freq[i] = 10000^(-i/32);  angle = s * inv_freq
//   x[i]    <- x[i]*cos    - x[i+32]*sin
//   x[i+32] <- x[i+32]*cos + x[i]*sin
// ---------------------------------------------------------------------------
__global__ __launch_bounds__(256)
void rope_kernel(float* __restrict__ Q, float* __restrict__ K)
{
    int idx = blockIdx.x * blockDim.x + threadIdx.x;
    if (idx >= S_LEN * NH * 32) return;
    int i = idx & 31;
    int h = (idx >> 5) & (NH - 1);
    int s = idx >> 9;

    float inv_freq = powf(10000.f, -(float)i / 32.f);
    float ang = (float)s * inv_freq;
    float c, sn;
    sincosf(ang, &sn, &c);

    long base = (long)s * DM + h * DK + i;

    float q1 = Q[base], q2 = Q[base + 32];
    Q[base]      = q1 * c - q2 * sn;
    Q[base + 32] = q2 * c + q1 * sn;

    float k1 = K[base], k2 = K[base + 32];
    K[base]      = k1 * c - k2 * sn;
    K[base + 32] = k2 * c + k1 * sn;
}

// ---------------------------------------------------------------------------
// Row softmax in place. One block per row (NH*S rows, ncols = S).
// ---------------------------------------------------------------------------
__global__ __launch_bounds__(256)
void softmax_kernel(float* __restrict__ attn, int ncols)
{
    float* p = attn + (long)blockIdx.x * ncols;
    const int tid = threadIdx.x;
    __shared__ float red[256];

    float m = -INFINITY;
    for (int c = tid; c < ncols; c += 256) m = fmaxf(m, p[c]);
    red[tid] = m;
    __syncthreads();
    for (int s = 128; s > 0; s >>= 1) {
        if (tid < s) red[tid] = fmaxf(red[tid], red[tid + s]);
        __syncthreads();
    }
    m = red[0];
    __syncthreads();

    float sum = 0.f;
    for (int c = tid; c < ncols; c += 256) {
        float e = expf(p[c] - m);
        p[c] = e;
        sum += e;
    }
    red[tid] = sum;
    __syncthreads();
    for (int s = 128; s > 0; s >>= 1) {
        if (tid < s) red[tid] += red[tid + s];
        __syncthreads();
    }
    float inv = 1.f / red[0];
    __syncthreads();

    for (int c = tid; c < ncols; c += 256) p[c] *= inv;
}

// ---------------------------------------------------------------------------
extern "C" void kernel_launch(void* const* d_in, const int* in_sizes, int n_in,
                              void* d_out, int out_size)
{
    const float* q   = (const float*)d_in[0];
    const float* k   = (const float*)d_in[1];
    const float* v   = (const float*)d_in[2];
    const float* w_q = (const float*)d_in[3];
    const float* w_k = (const float*)d_in[4];
    const float* w_v = (const float*)d_in[5];
    const float* w_o = (const float*)d_in[6];
    const float* b_o = (const float*)d_in[7];

    float* out  = (float*)d_out;
    float* attn = out + (long)S_LEN * DM;   // attn region follows `out`

    float *pQ, *pK, *pV, *pC;
    cudaGetSymbolAddress((void**)&pQ, g_Q);
    cudaGetSymbolAddress((void**)&pK, g_K);
    cudaGetSymbolAddress((void**)&pV, g_V);
    cudaGetSymbolAddress((void**)&pC, g_ctx);

    const dim3 blk(256);

    // 1) Projections: [S,DM] @ W^T -> [S,DM]
    dim3 gproj(DM / 64, S_LEN / 64, 1);
    sgemm_kernel<true, false><<<gproj, blk>>>(q, w_q, nullptr, pQ,
        S_LEN, DM, DM, DM, DM, DM, 0, 0, 0, 1.f);
    sgemm_kernel<true, false><<<gproj, blk>>>(k, w_k, nullptr, pK,
        S_LEN, DM, DM, DM, DM, DM, 0, 0, 0, 1.f);
    sgemm_kernel<true, false><<<gproj, blk>>>(v, w_v, nullptr, pV,
        S_LEN, DM, DM, DM, DM, DM, 0, 0, 0, 1.f);

    // 2) RoPE on Q and K in place
    int nrope = S_LEN * NH * 32;
    rope_kernel<<<(nrope + 255) / 256, blk>>>(pQ, pK);

    // 3) Scores per head: Qh @ Kh^T / 8 -> attn region (pre-softmax)
    dim3 gscore(S_LEN / 64, S_LEN / 64, NH);
    sgemm_kernel<true, false><<<gscore, blk>>>(pQ, pK, nullptr, attn,
        S_LEN, S_LEN, DK, DM, DM, S_LEN,
        (long)DK, (long)DK, (long)S_LEN * S_LEN, 0.125f);

    // 4) Softmax rows in place
    softmax_kernel<<<NH * S_LEN, blk>>>(attn, S_LEN);

    // 5) Context per head: attn @ Vh -> ctx (interleaved back to [S, DM])
    dim3 gctx(DK / 64, S_LEN / 64, NH);
    sgemm_kernel<false, false><<<gctx, blk>>>(attn, pV, nullptr, pC,
        S_LEN, DK, S_LEN, S_LEN, DM, DM,
        (long)S_LEN * S_LEN, (long)DK, (long)DK, 1.f);

    // 6) Output projection: ctx @ w_o^T + b_o -> out
    dim3 gout(DM / 64, S_LEN / 64, 1);
    sgemm_kernel<true, true><<<gout, blk>>>(pC, w_o, b_o, out,
        S_LEN, DM, DM, DM, DM, DM, 0, 0, 0, 1.f);
}

// round 3
// speedup vs baseline: 2.0041x; 2.0041x over previous
#include <cuda_runtime.h>
#include <math.h>

#define S_LEN 2048
#define DM    1024
#define NH    16
#define DK    64

// Scratch (no allocations allowed). 4 x 8 MB fp32.
__device__ float g_Q[S_LEN * DM];
__device__ float g_K[S_LEN * DM];
__device__ float g_V[S_LEN * DM];
__device__ float g_ctx[S_LEN * DM];

// ---------------------------------------------------------------------------
// Tiled SGEMM, register-prefetch double buffered, float4 everywhere.
//   C[m][n] = alpha * sum_k A[m][k] * B'[k][n]  (+ bias[n])
//   TRANSB=true :  B'[k][n] = B[n][k]
//   TRANSB=false:  B'[k][n] = B[k][n]
// Batched over blockIdx.z via element strides sA/sB/sC.
// All dims are multiples of tile sizes; K multiple of BK; no bounds checks.
// ---------------------------------------------------------------------------
template <int BM, int BN, int BK, int TM, int TN, bool TRANSB, bool BIAS>
__global__ __launch_bounds__(256)
void sgemm(const float* __restrict__ A, const float* __restrict__ B,
           const float* __restrict__ bias, float* __restrict__ C,
           int K, int lda, int ldb, int ldc,
           long sA, long sB, long sC, float alpha)
{
    constexpr int NT = (BM / TM) * (BN / TN);
    static_assert(NT == 256, "256 threads expected");
    constexpr int KQ = BK / 4;                        // float4 per k-chunk row
    constexpr int NQ = BN / 4;                        // float4 per n-row (NN)
    constexpr int LA = (BM * BK / 4) / NT;            // A float4 per thread
    constexpr int LB = (BN * BK / 4) / NT;            // B float4 per thread

    __shared__ float As[BK][BM];
    __shared__ float Bs[BK][BN];

    A += (long)blockIdx.z * sA;
    B += (long)blockIdx.z * sB;
    C += (long)blockIdx.z * sC;

    const int row0 = blockIdx.y * BM;
    const int col0 = blockIdx.x * BN;
    const int tid  = threadIdx.x;
    const int tx   = tid % (BN / TN);
    const int ty   = tid / (BN / TN);

    float4 pa[LA], pb[LB];
    float acc[TM][TN] = {};

    auto load_regs = [&](int k0) {
#pragma unroll
        for (int t = 0; t < LA; t++) {
            int f = tid + t * NT, m = f / KQ, kq = f % KQ;
            pa[t] = *reinterpret_cast<const float4*>(
                        &A[(long)(row0 + m) * lda + k0 + kq * 4]);
        }
#pragma unroll
        for (int t = 0; t < LB; t++) {
            int f = tid + t * NT;
            if (TRANSB) {
                int n = f / KQ, kq = f % KQ;
                pb[t] = *reinterpret_cast<const float4*>(
                            &B[(long)(col0 + n) * ldb + k0 + kq * 4]);
            } else {
                int kk = f / NQ, nq = f % NQ;
                pb[t] = *reinterpret_cast<const float4*>(
                            &B[(long)(k0 + kk) * ldb + col0 + nq * 4]);
            }
        }
    };

    auto store_smem = [&]() {
#pragma unroll
        for (int t = 0; t < LA; t++) {
            int f = tid + t * NT, m = f / KQ, kq = f % KQ;
            As[kq * 4 + 0][m] = pa[t].x;
            As[kq * 4 + 1][m] = pa[t].y;
            As[kq * 4 + 2][m] = pa[t].z;
            As[kq * 4 + 3][m] = pa[t].w;
        }
#pragma unroll
        for (int t = 0; t < LB; t++) {
            int f = tid + t * NT;
            if (TRANSB) {
                int n = f / KQ, kq = f % KQ;
                Bs[kq * 4 + 0][n] = pb[t].x;
                Bs[kq * 4 + 1][n] = pb[t].y;
                Bs[kq * 4 + 2][n] = pb[t].z;
                Bs[kq * 4 + 3][n] = pb[t].w;
            } else {
                int kk = f / NQ, nq = f % NQ;
                reinterpret_cast<float4*>(&Bs[kk][0])[nq] = pb[t];
            }
        }
    };

    auto compute = [&]() {
#pragma unroll
        for (int k = 0; k < BK; k++) {
            float a[TM], b[TN];
#pragma unroll
            for (int i = 0; i < TM / 4; i++)
                reinterpret_cast<float4*>(a)[i] =
                    reinterpret_cast<const float4*>(&As[k][0])[ty * (TM / 4) + i];
#pragma unroll
            for (int j = 0; j < TN / 4; j++)
                reinterpret_cast<float4*>(b)[j] =
                    reinterpret_cast<const float4*>(&Bs[k][0])[tx * (TN / 4) + j];
#pragma unroll
            for (int i = 0; i < TM; i++)
#pragma unroll
                for (int j = 0; j < TN; j++)
                    acc[i][j] = fmaf(a[i], b[j], acc[i][j]);
        }
    };

    load_regs(0);
    store_smem();
    __syncthreads();

    for (int k0 = BK; k0 < K; k0 += BK) {
        load_regs(k0);     // global loads for next tile issue early
        compute();         // compute on current smem tile
        __syncthreads();
        store_smem();
        __syncthreads();
    }
    compute();

    // Epilogue: vectorized stores
#pragma unroll
    for (int i = 0; i < TM; i++) {
        int m = row0 + ty * TM + i;
#pragma unroll
        for (int jq = 0; jq < TN / 4; jq++) {
            int n = col0 + tx * TN + jq * 4;
            float4 o;
            o.x = acc[i][jq * 4 + 0] * alpha;
            o.y = acc[i][jq * 4 + 1] * alpha;
            o.z = acc[i][jq * 4 + 2] * alpha;
            o.w = acc[i][jq * 4 + 3] * alpha;
            if (BIAS) {
                o.x += bias[n + 0];
                o.y += bias[n + 1];
                o.z += bias[n + 2];
                o.w += bias[n + 3];
            }
            *reinterpret_cast<float4*>(&C[(long)m * ldc + n]) = o;
        }
    }
}

// ---------------------------------------------------------------------------
// RoPE in place on Q and K.
// ---------------------------------------------------------------------------
__global__ __launch_bounds__(256)
void rope_kernel(float* __restrict__ Q, float* __restrict__ K)
{
    int idx = blockIdx.x * blockDim.x + threadIdx.x;
    if (idx >= S_LEN * NH * 32) return;
    int i = idx & 31;
    int h = (idx >> 5) & (NH - 1);
    int s = idx >> 9;

    float inv_freq = powf(10000.f, -(float)i / 32.f);
    float ang = (float)s * inv_freq;
    float c, sn;
    sincosf(ang, &sn, &c);

    long base = (long)s * DM + h * DK + i;

    float q1 = Q[base], q2 = Q[base + 32];
    Q[base]      = q1 * c - q2 * sn;
    Q[base + 32] = q2 * c + q1 * sn;

    float k1 = K[base], k2 = K[base + 32];
    K[base]      = k1 * c - k2 * sn;
    K[base + 32] = k2 * c + k1 * sn;
}

// ---------------------------------------------------------------------------
// Row softmax in place, row fully register-resident.
// One block per row (NH*S rows), 256 threads, 8 floats per thread.
// Single global read + single global write of the row.
// ---------------------------------------------------------------------------
__global__ __launch_bounds__(256)
void softmax_kernel(float* __restrict__ attn)
{
    float4* p = reinterpret_cast<float4*>(attn + (long)blockIdx.x * S_LEN);
    const int tid  = threadIdx.x;
    const int warp = tid >> 5, lane = tid & 31;
    __shared__ float redm[8], reds[8];

    float4 v0 = p[tid];
    float4 v1 = p[tid + 256];

    // --- row max ---
    float m = fmaxf(fmaxf(fmaxf(v0.x, v0.y), fmaxf(v0.z, v0.w)),
                    fmaxf(fmaxf(v1.x, v1.y), fmaxf(v1.z, v1.w)));
#pragma unroll
    for (int o = 16; o > 0; o >>= 1)
        m = fmaxf(m, __shfl_xor_sync(0xffffffffu, m, o));
    if (lane == 0) redm[warp] = m;
    __syncthreads();
    if (tid == 0) {
        float mm = redm[0];
#pragma unroll
        for (int w = 1; w < 8; w++) mm = fmaxf(mm, redm[w]);
        redm[0] = mm;
    }
    __syncthreads();
    m = redm[0];

    // --- exp + row sum ---
    v0.x = expf(v0.x - m); v0.y = expf(v0.y - m);
    v0.z = expf(v0.z - m); v0.w = expf(v0.w - m);
    v1.x = expf(v1.x - m); v1.y = expf(v1.y - m);
    v1.z = expf(v1.z - m); v1.w = expf(v1.w - m);
    float s = (v0.x + v0.y + v0.z + v0.w) + (v1.x + v1.y + v1.z + v1.w);
#pragma unroll
    for (int o = 16; o > 0; o >>= 1)
        s += __shfl_xor_sync(0xffffffffu, s, o);
    if (lane == 0) reds[warp] = s;
    __syncthreads();
    if (tid == 0) {
        float ss = reds[0];
#pragma unroll
        for (int w = 1; w < 8; w++) ss += reds[w];
        reds[0] = ss;
    }
    __syncthreads();
    float inv = 1.f / reds[0];

    v0.x *= inv; v0.y *= inv; v0.z *= inv; v0.w *= inv;
    v1.x *= inv; v1.y *= inv; v1.z *= inv; v1.w *= inv;
    p[tid]       = v0;
    p[tid + 256] = v1;
}

// ---------------------------------------------------------------------------
extern "C" void kernel_launch(void* const* d_in, const int* in_sizes, int n_in,
                              void* d_out, int out_size)
{
    const float* q   = (const float*)d_in[0];
    const float* k   = (const float*)d_in[1];
    const float* v   = (const float*)d_in[2];
    const float* w_q = (const float*)d_in[3];
    const float* w_k = (const float*)d_in[4];
    const float* w_v = (const float*)d_in[5];
    const float* w_o = (const float*)d_in[6];
    const float* b_o = (const float*)d_in[7];

    float* out  = (float*)d_out;
    float* attn = out + (long)S_LEN * DM;   // attn region follows `out`

    float *pQ, *pK, *pV, *pC;
    cudaGetSymbolAddress((void**)&pQ, g_Q);
    cudaGetSymbolAddress((void**)&pK, g_K);
    cudaGetSymbolAddress((void**)&pV, g_V);
    cudaGetSymbolAddress((void**)&pC, g_ctx);

    const dim3 blk(256);

    // 1) Projections: [S,DM] @ W^T -> [S,DM]
    dim3 gproj(DM / 128, S_LEN / 128, 1);
    sgemm<128,128,16,8,8,true,false><<<gproj, blk>>>(q, w_q, nullptr, pQ,
        DM, DM, DM, DM, 0, 0, 0, 1.f);
    sgemm<128,128,16,8,8,true,false><<<gproj, blk>>>(k, w_k, nullptr, pK,
        DM, DM, DM, DM, 0, 0, 0, 1.f);
    sgemm<128,128,16,8,8,true,false><<<gproj, blk>>>(v, w_v, nullptr, pV,
        DM, DM, DM, DM, 0, 0, 0, 1.f);

    // 2) RoPE on Q and K in place
    int nrope = S_LEN * NH * 32;
    rope_kernel<<<(nrope + 255) / 256, blk>>>(pQ, pK);

    // 3) Scores per head: Qh @ Kh^T / 8 -> attn region (pre-softmax)
    dim3 gscore(S_LEN / 128, S_LEN / 128, NH);
    sgemm<128,128,16,8,8,true,false><<<gscore, blk>>>(pQ, pK, nullptr, attn,
        DK, DM, DM, S_LEN,
        (long)DK, (long)DK, (long)S_LEN * S_LEN, 0.125f);

    // 4) Softmax rows in place (register-resident rows)
    softmax_kernel<<<NH * S_LEN, blk>>>(attn);

    // 5) Context per head: attn @ Vh -> ctx (interleaved back to [S, DM])
    dim3 gctx(1, S_LEN / 128, NH);
    sgemm<128,64,16,8,4,false,false><<<gctx, blk>>>(attn, pV, nullptr, pC,
        S_LEN, S_LEN, DM, DM,
        (long)S_LEN * S_LEN, (long)DK, (long)DK, 1.f);

    // 6) Output projection: ctx @ w_o^T + b_o -> out
    dim3 gout(DM / 128, S_LEN / 128, 1);
    sgemm<128,128,16,8,8,true,true><<<gout, blk>>>(pC, w_o, b_o, out,
        DM, DM, DM, DM, 0, 0, 0, 1.f);
}

// round 8
// speedup vs baseline: 3.1951x; 1.5942x over previous
#include <cuda_runtime.h>
#include <cuda_bf16.h>
#include <math.h>
#include <stdint.h>

#define S_LEN 2048
#define DM    1024
#define NH    16
#define DK    64

// Scratch (no allocations allowed). 4 x 8 MB fp32.
__device__ float g_Q[S_LEN * DM];
__device__ float g_K[S_LEN * DM];
__device__ float g_V[S_LEN * DM];
__device__ float g_ctx[S_LEN * DM];

// ---------------------------------------------------------------------------
// mma.sync m16n8k16 bf16 (arch-portable tensor-core path, sm_80+)
// ---------------------------------------------------------------------------
__device__ __forceinline__ void mma16816(float* d, const uint32_t* a,
                                         const uint32_t* b) {
    asm volatile(
        "mma.sync.aligned.m16n8k16.row.col.f32.bf16.bf16.f32 "
        "{%0,%1,%2,%3}, {%4,%5,%6,%7}, {%8,%9}, {%0,%1,%2,%3};\n"
        : "+f"(d[0]), "+f"(d[1]), "+f"(d[2]), "+f"(d[3])
        : "r"(a[0]), "r"(a[1]), "r"(a[2]), "r"(a[3]), "r"(b[0]), "r"(b[1]));
}

// Split two consecutive fp32 into packed bf16x2 hi and lo (hi=bf16(x), lo=bf16(x-hi))
__device__ __forceinline__ void split2(float f0, float f1,
                                       uint32_t& hi, uint32_t& lo) {
    __nv_bfloat16 h0 = __float2bfloat16(f0);
    __nv_bfloat16 h1 = __float2bfloat16(f1);
    float r0 = f0 - __bfloat162float(h0);
    float r1 = f1 - __bfloat162float(h1);
    __nv_bfloat16 l0 = __float2bfloat16(r0);
    __nv_bfloat16 l1 = __float2bfloat16(r1);
    hi = (uint32_t)*reinterpret_cast<uint16_t*>(&h0) |
         ((uint32_t)*reinterpret_cast<uint16_t*>(&h1) << 16);
    lo = (uint32_t)*reinterpret_cast<uint16_t*>(&l0) |
         ((uint32_t)*reinterpret_cast<uint16_t*>(&l1) << 16);
}

// ===========================================================================
// Split-bf16 tensor-core GEMM.  C[m][n] = alpha*sum_k A[m][k]*B'[k][n] (+bias)
//   TRANSB=true : B'[k][n] = B[n][k]  (both operands K-major)
//   TRANSB=false: B'[k][n] = B[k][n]  (B N-major; transposed during STS)
// BM=128, BN in {128,64}, BK=32. 256 threads = 8 warps.
// Batched over blockIdx.z via element strides sA/sB/sC.
// ===========================================================================
template <int BN, bool TRANSB, bool BIAS>
__global__ __launch_bounds__(256)
void mma_gemm(const float* __restrict__ A, const float* __restrict__ B,
              const float* __restrict__ bias, float* __restrict__ C,
              int K, int lda, int ldb, int ldc,
              long sA, long sB, long sC, float alpha)
{
    constexpr int BM = 128, BK = 32;
    constexpr int WARPS_N = (BN == 128) ? 4 : 2;
    constexpr int WARPS_M = 8 / WARPS_N;
    constexpr int WM = BM / WARPS_M;     // 64 or 32
    constexpr int WN = BN / WARPS_N;     // 32
    constexpr int MF = WM / 16;          // 4 or 2
    constexpr int NF = WN / 8;           // 4
    constexpr int LDS_R = BK + 2;        // padded row (bf16 units) -> no conflicts

    __shared__ __nv_bfloat16 AsH[BM][LDS_R], AsL[BM][LDS_R];
    __shared__ __nv_bfloat16 BsH[BN][LDS_R], BsL[BN][LDS_R];

    const int tid = threadIdx.x;
    const int wid = tid >> 5, lane = tid & 31;
    const int wm = wid / WARPS_N, wn = wid % WARPS_N;
    const int grp = lane >> 2, tig = lane & 3;

    A += (long)blockIdx.z * sA;
    B += (long)blockIdx.z * sB;
    C += (long)blockIdx.z * sC;
    const int row0 = blockIdx.y * BM;
    const int col0 = blockIdx.x * BN;

    float acc[MF][NF][4] = {};

    constexpr int LA = (BM * BK / 4) / 256;                       // 4
    constexpr int LB = (TRANSB ? (BN * BK / 4) : (BK * BN / 4)) / 256;
    float4 pa[LA], pb[LB];

    auto load_regs = [&](int k0) {
#pragma unroll
        for (int t = 0; t < LA; t++) {
            int f = tid + t * 256, m = f >> 3, kq = f & 7;
            pa[t] = *reinterpret_cast<const float4*>(
                        &A[(long)(row0 + m) * lda + k0 + kq * 4]);
        }
#pragma unroll
        for (int t = 0; t < LB; t++) {
            int f = tid + t * 256;
            if (TRANSB) {
                int n = f >> 3, kq = f & 7;
                pb[t] = *reinterpret_cast<const float4*>(
                            &B[(long)(col0 + n) * ldb + k0 + kq * 4]);
            } else {
                int kk = f / (BN / 4), nq = f % (BN / 4);
                pb[t] = *reinterpret_cast<const float4*>(
                            &B[(long)(k0 + kk) * ldb + col0 + nq * 4]);
            }
        }
    };

    auto store_smem = [&]() {
#pragma unroll
        for (int t = 0; t < LA; t++) {
            int f = tid + t * 256, m = f >> 3, kq = f & 7;
            uint32_t h0, l0, h1, l1;
            split2(pa[t].x, pa[t].y, h0, l0);
            split2(pa[t].z, pa[t].w, h1, l1);
            uint32_t* ph = reinterpret_cast<uint32_t*>(&AsH[m][kq * 4]);
            uint32_t* pl = reinterpret_cast<uint32_t*>(&AsL[m][kq * 4]);
            ph[0] = h0; ph[1] = h1;
            pl[0] = l0; pl[1] = l1;
        }
#pragma unroll
        for (int t = 0; t < LB; t++) {
            int f = tid + t * 256;
            if (TRANSB) {
                int n = f >> 3, kq = f & 7;
                uint32_t h0, l0, h1, l1;
                split2(pb[t].x, pb[t].y, h0, l0);
                split2(pb[t].z, pb[t].w, h1, l1);
                uint32_t* ph = reinterpret_cast<uint32_t*>(&BsH[n][kq * 4]);
                uint32_t* pl = reinterpret_cast<uint32_t*>(&BsL[n][kq * 4]);
                ph[0] = h0; ph[1] = h1;
                pl[0] = l0; pl[1] = l1;
            } else {
                int kk = f / (BN / 4), nq = f % (BN / 4);
                float fv[4] = {pb[t].x, pb[t].y, pb[t].z, pb[t].w};
#pragma unroll
                for (int j = 0; j < 4; j++) {
                    __nv_bfloat16 h = __float2bfloat16(fv[j]);
                    float r = fv[j] - __bfloat162float(h);
                    BsH[nq * 4 + j][kk] = h;
                    BsL[nq * 4 + j][kk] = __float2bfloat16(r);
                }
            }
        }
    };

    auto compute = [&]() {
#pragma unroll
        for (int ks = 0; ks < 2; ks++) {
            const int kb = ks * 16 + tig * 2;
            uint32_t ah[MF][4], al[MF][4], bh[NF][2], bl[NF][2];
#pragma unroll
            for (int i = 0; i < MF; i++) {
                int r = wm * WM + i * 16 + grp;
                ah[i][0] = *reinterpret_cast<const uint32_t*>(&AsH[r][kb]);
                ah[i][1] = *reinterpret_cast<const uint32_t*>(&AsH[r + 8][kb]);
                ah[i][2] = *reinterpret_cast<const uint32_t*>(&AsH[r][kb + 8]);
                ah[i][3] = *reinterpret_cast<const uint32_t*>(&AsH[r + 8][kb + 8]);
                al[i][0] = *reinterpret_cast<const uint32_t*>(&AsL[r][kb]);
                al[i][1] = *reinterpret_cast<const uint32_t*>(&AsL[r + 8][kb]);
                al[i][2] = *reinterpret_cast<const uint32_t*>(&AsL[r][kb + 8]);
                al[i][3] = *reinterpret_cast<const uint32_t*>(&AsL[r + 8][kb + 8]);
            }
#pragma unroll
            for (int j = 0; j < NF; j++) {
                int n = wn * WN + j * 8 + grp;
                bh[j][0] = *reinterpret_cast<const uint32_t*>(&BsH[n][kb]);
                bh[j][1] = *reinterpret_cast<const uint32_t*>(&BsH[n][kb + 8]);
                bl[j][0] = *reinterpret_cast<const uint32_t*>(&BsL[n][kb]);
                bl[j][1] = *reinterpret_cast<const uint32_t*>(&BsL[n][kb + 8]);
            }
#pragma unroll
            for (int i = 0; i < MF; i++)
#pragma unroll
                for (int j = 0; j < NF; j++) {
                    mma16816(acc[i][j], ah[i], bh[j]);
                    mma16816(acc[i][j], al[i], bh[j]);
                    mma16816(acc[i][j], ah[i], bl[j]);
                }
        }
    };

    const int nch = K / BK;
    load_regs(0);
    store_smem();
    __syncthreads();
    for (int c = 0; c < nch; c++) {
        if (c + 1 < nch) load_regs((c + 1) * BK);
        compute();
        __syncthreads();
        if (c + 1 < nch) {
            store_smem();
            __syncthreads();
        }
    }

    // Epilogue: fragment rows (grp, grp+8), cols 2*tig..2*tig+1 -> float2 stores
#pragma unroll
    for (int i = 0; i < MF; i++) {
        int r = row0 + wm * WM + i * 16 + grp;
#pragma unroll
        for (int j = 0; j < NF; j++) {
            int n = col0 + wn * WN + j * 8 + tig * 2;
            float2 v0, v1;
            v0.x = acc[i][j][0] * alpha;
            v0.y = acc[i][j][1] * alpha;
            v1.x = acc[i][j][2] * alpha;
            v1.y = acc[i][j][3] * alpha;
            if (BIAS) {
                v0.x += bias[n];     v0.y += bias[n + 1];
                v1.x += bias[n];     v1.y += bias[n + 1];
            }
            *reinterpret_cast<float2*>(&C[(long)r * ldc + n])       = v0;
            *reinterpret_cast<float2*>(&C[(long)(r + 8) * ldc + n]) = v1;
        }
    }
}

// ---------------------------------------------------------------------------
// RoPE in place on Q and K.
// ---------------------------------------------------------------------------
__global__ __launch_bounds__(256)
void rope_kernel(float* __restrict__ Q, float* __restrict__ K)
{
    int idx = blockIdx.x * blockDim.x + threadIdx.x;
    if (idx >= S_LEN * NH * 32) return;
    int i = idx & 31;
    int h = (idx >> 5) & (NH - 1);
    int s = idx >> 9;

    float inv_freq = powf(10000.f, -(float)i / 32.f);
    float ang = (float)s * inv_freq;
    float c, sn;
    sincosf(ang, &sn, &c);

    long base = (long)s * DM + h * DK + i;

    float q1 = Q[base], q2 = Q[base + 32];
    Q[base]      = q1 * c - q2 * sn;
    Q[base + 32] = q2 * c + q1 * sn;

    float k1 = K[base], k2 = K[base + 32];
    K[base]      = k1 * c - k2 * sn;
    K[base + 32] = k2 * c + k1 * sn;
}

// ---------------------------------------------------------------------------
// Row softmax in place, row fully register-resident (2048 cols).
// ---------------------------------------------------------------------------
__global__ __launch_bounds__(256)
void softmax_kernel(float* __restrict__ attn)
{
    float4* p = reinterpret_cast<float4*>(attn + (long)blockIdx.x * S_LEN);
    const int tid  = threadIdx.x;
    const int warp = tid >> 5, lane = tid & 31;
    __shared__ float redm[8], reds[8];

    float4 v0 = p[tid];
    float4 v1 = p[tid + 256];

    float m = fmaxf(fmaxf(fmaxf(v0.x, v0.y), fmaxf(v0.z, v0.w)),
                    fmaxf(fmaxf(v1.x, v1.y), fmaxf(v1.z, v1.w)));
#pragma unroll
    for (int o = 16; o > 0; o >>= 1)
        m = fmaxf(m, __shfl_xor_sync(0xffffffffu, m, o));
    if (lane == 0) redm[warp] = m;
    __syncthreads();
    if (tid == 0) {
        float mm = redm[0];
#pragma unroll
        for (int w = 1; w < 8; w++) mm = fmaxf(mm, redm[w]);
        redm[0] = mm;
    }
    __syncthreads();
    m = redm[0];

    v0.x = expf(v0.x - m); v0.y = expf(v0.y - m);
    v0.z = expf(v0.z - m); v0.w = expf(v0.w - m);
    v1.x = expf(v1.x - m); v1.y = expf(v1.y - m);
    v1.z = expf(v1.z - m); v1.w = expf(v1.w - m);
    float s = (v0.x + v0.y + v0.z + v0.w) + (v1.x + v1.y + v1.z + v1.w);
#pragma unroll
    for (int o = 16; o > 0; o >>= 1)
        s += __shfl_xor_sync(0xffffffffu, s, o);
    if (lane == 0) reds[warp] = s;
    __syncthreads();
    if (tid == 0) {
        float ss = reds[0];
#pragma unroll
        for (int w = 1; w < 8; w++) ss += reds[w];
        reds[0] = ss;
    }
    __syncthreads();
    float inv = 1.f / reds[0];

    v0.x *= inv; v0.y *= inv; v0.z *= inv; v0.w *= inv;
    v1.x *= inv; v1.y *= inv; v1.z *= inv; v1.w *= inv;
    p[tid]       = v0;
    p[tid + 256] = v1;
}

// ---------------------------------------------------------------------------
extern "C" void kernel_launch(void* const* d_in, const int* in_sizes, int n_in,
                              void* d_out, int out_size)
{
    const float* q   = (const float*)d_in[0];
    const float* k   = (const float*)d_in[1];
    const float* v   = (const float*)d_in[2];
    const float* w_q = (const float*)d_in[3];
    const float* w_k = (const float*)d_in[4];
    const float* w_v = (const float*)d_in[5];
    const float* w_o = (const float*)d_in[6];
    const float* b_o = (const float*)d_in[7];

    float* out  = (float*)d_out;
    float* attn = out + (long)S_LEN * DM;   // attn region follows `out`

    float *pQ, *pK, *pV, *pC;
    cudaGetSymbolAddress((void**)&pQ, g_Q);
    cudaGetSymbolAddress((void**)&pK, g_K);
    cudaGetSymbolAddress((void**)&pV, g_V);
    cudaGetSymbolAddress((void**)&pC, g_ctx);

    const dim3 blk(256);

    // 1) Projections: [S,DM] @ W^T -> [S,DM]
    dim3 gproj(DM / 128, S_LEN / 128, 1);
    mma_gemm<128, true, false><<<gproj, blk>>>(q, w_q, nullptr, pQ,
        DM, DM, DM, DM, 0, 0, 0, 1.f);
    mma_gemm<128, true, false><<<gproj, blk>>>(k, w_k, nullptr, pK,
        DM, DM, DM, DM, 0, 0, 0, 1.f);
    mma_gemm<128, true, false><<<gproj, blk>>>(v, w_v, nullptr, pV,
        DM, DM, DM, DM, 0, 0, 0, 1.f);

    // 2) RoPE on Q and K in place
    int nrope = S_LEN * NH * 32;
    rope_kernel<<<(nrope + 255) / 256, 256>>>(pQ, pK);

    // 3) Scores per head: Qh @ Kh^T / 8 -> attn region (pre-softmax)
    dim3 gscore(S_LEN / 128, S_LEN / 128, NH);
    mma_gemm<128, true, false><<<gscore, blk>>>(pQ, pK, nullptr, attn,
        DK, DM, DM, S_LEN,
        (long)DK, (long)DK, (long)S_LEN * S_LEN, 0.125f);

    // 4) Softmax rows in place
    softmax_kernel<<<NH * S_LEN, 256>>>(attn);

    // 5) Context per head: attn @ Vh -> ctx (interleaved back to [S, DM])
    dim3 gctx(1, S_LEN / 128, NH);
    mma_gemm<64, false, false><<<gctx, blk>>>(attn, pV, nullptr, pC,
        S_LEN, S_LEN, DM, DM,
        (long)S_LEN * S_LEN, (long)DK, (long)DK, 1.f);

    // 6) Output projection: ctx @ w_o^T + b_o -> out
    dim3 gout(DM / 128, S_LEN / 128, 1);
    mma_gemm<128, true, true><<<gout, blk>>>(pC, w_o, b_o, out,
        DM, DM, DM, DM, 0, 0, 0, 1.f);
}